// round 11
// baseline (speedup 1.0000x reference)
#include <cuda_runtime.h>

// network_5299989643808: per-(z,zp)-pair tiny MLP over batch B.
// R9: all tanh via single-MUFU tanh.approx.f32. R8 measured that HW tanh on
// this network's small arguments is ~1e-7-accurate (sigmoid-head swap moved
// rel_err 1.5e-7 -> 3e-7 only), so the LN-amplification concern is void.
// Saves 8 MUFU + ~24 instrs per element vs R8 (MUFU was ~half the issue load).

static constexpr int ZZ  = 64;    // zones
static constexpr int BCH = 128;   // batch elements per block (y-dim chunk)

__device__ __forceinline__ float fast_rsqrt(float x) {
    float r; asm("rsqrt.approx.f32 %0, %1;" : "=f"(r) : "f"(x)); return r;
}
__device__ __forceinline__ float fast_rcp(float x) {
    float r; asm("rcp.approx.f32 %0, %1;" : "=f"(r) : "f"(x)); return r;
}
// HW tanh: 1 MUFU op; ~1e-7 accurate for this network's small arguments
// (empirically validated in R8 on the sigmoid head).
__device__ __forceinline__ float tanh_hw(float x) {
    float r; asm("tanh.approx.f32 %0, %1;" : "=f"(r) : "f"(x)); return r;
}
// Streaming 128-bit store (output is write-once, never re-read).
__device__ __forceinline__ void store_cs(float4* p, float4 v) {
    asm volatile("st.global.cs.v4.f32 [%0], {%1, %2, %3, %4};"
                 :: "l"(p), "f"(v.x), "f"(v.y), "f"(v.z), "f"(v.w) : "memory");
}

__global__ __launch_bounds__(128, 4)
void mlp_pairs_kernel(
    const float* __restrict__ nt,
    const float* __restrict__ W1,  const float* __restrict__ b1,
    const float* __restrict__ g1,  const float* __restrict__ be1,
    const float* __restrict__ W2,  const float* __restrict__ b2,
    const float* __restrict__ g2,  const float* __restrict__ be2,
    const float* __restrict__ Wpi, const float* __restrict__ bpi,
    const float* __restrict__ Wxi, const float* __restrict__ bxi,
    float* __restrict__ out, int nB)
{
    const int p  = blockIdx.x * blockDim.x + threadIdx.x;  // pair index 0..4095
    const int z  = p >> 6;
    const int zp = p & 63;

    // ---- Load weights for this pair, folding LN gamma/beta forward ----
    const float4* W1v = reinterpret_cast<const float4*>(W1) + (size_t)p * 2;
    float4 w1a = W1v[0];
    float4 w1b = W1v[1];
    float4 b1v = reinterpret_cast<const float4*>(b1)[p];
    float4 g1v = reinterpret_cast<const float4*>(g1)[p];
    float4 e1v = reinterpret_cast<const float4*>(be1)[p];
    float4 g2v = reinterpret_cast<const float4*>(g2)[p];
    float4 e2v = reinterpret_cast<const float4*>(be2)[p];

    const float g1a[4] = {g1v.x, g1v.y, g1v.z, g1v.w};
    const float e1a[4] = {e1v.x, e1v.y, e1v.z, e1v.w};
    const float g2a[4] = {g2v.x, g2v.y, g2v.z, g2v.w};
    const float e2a[4] = {e2v.x, e2v.y, e2v.z, e2v.w};

    // W2 folded: W2f[i][k] = W2[i][k]*g1[i];  b2f[k] = b2[k] + sum_i be1[i]*W2[i][k]
    float W2f[16], b2f[4];
    {
        float4 b2v = reinterpret_cast<const float4*>(b2)[p];
        b2f[0] = b2v.x; b2f[1] = b2v.y; b2f[2] = b2v.z; b2f[3] = b2v.w;
        const float4* W2v = reinterpret_cast<const float4*>(W2) + (size_t)p * 4;
        #pragma unroll
        for (int i = 0; i < 4; ++i) {
            float4 row = W2v[i];
            float rr[4] = {row.x, row.y, row.z, row.w};
            #pragma unroll
            for (int k = 0; k < 4; ++k) {
                W2f[i * 4 + k] = rr[k] * g1a[i];
                b2f[k] = fmaf(e1a[i], rr[k], b2f[k]);
            }
        }
    }
    // Heads folded with g2/be2. Sigmoid head additionally pre-scaled by 0.5:
    // sigmoid(x) = 0.5*tanh(x/2) + 0.5, so fold the /2 into Wxf/bxf.
    float Wpf[16], bpf[4], Wxf[16], bxf[4];
    {
        float4 bpv = reinterpret_cast<const float4*>(bpi)[p];
        float4 bxv = reinterpret_cast<const float4*>(bxi)[p];
        bpf[0] = bpv.x; bpf[1] = bpv.y; bpf[2] = bpv.z; bpf[3] = bpv.w;
        bxf[0] = 0.5f * bxv.x; bxf[1] = 0.5f * bxv.y;
        bxf[2] = 0.5f * bxv.z; bxf[3] = 0.5f * bxv.w;
        const float4* Wpv = reinterpret_cast<const float4*>(Wpi) + (size_t)p * 4;
        const float4* Wxv = reinterpret_cast<const float4*>(Wxi) + (size_t)p * 4;
        #pragma unroll
        for (int k = 0; k < 4; ++k) {
            float4 rp = Wpv[k];
            float rpa[4] = {rp.x, rp.y, rp.z, rp.w};
            float4 rx = Wxv[k];
            float rxa[4] = {rx.x, rx.y, rx.z, rx.w};
            const float g2h = 0.5f * g2a[k];
            const float e2h = 0.5f * e2a[k];
            #pragma unroll
            for (int o = 0; o < 4; ++o) {
                Wpf[k * 4 + o] = rpa[o] * g2a[k];
                bpf[o] = fmaf(e2a[k], rpa[o], bpf[o]);
                Wxf[k * 4 + o] = rxa[o] * g2h;
                bxf[o] = fmaf(e2h, rxa[o], bxf[o]);
            }
        }
    }

    const float w1x[4] = {w1a.x, w1a.y, w1a.z, w1a.w};
    const float w1y[4] = {w1b.x, w1b.y, w1b.z, w1b.w};
    const float b1a[4] = {b1v.x, b1v.y, b1v.z, b1v.w};

    const size_t N4   = (size_t)nB * ZZ * ZZ;      // float4 count per tensor
    const int    STEP = ZZ * ZZ;                   // float4 stride per batch element

    const int b0   = blockIdx.y * BCH;
    const int bend = (b0 + BCH < nB) ? (b0 + BCH) : nB;

    // Incremented pointers: no per-iteration index arithmetic.
    float4* pPi = reinterpret_cast<float4*>(out) + (size_t)b0 * STEP + ((size_t)z * ZZ + zp);
    float4* pLp = pPi + N4;
    float4* pXi = pPi + 2 * N4;
    const float* pz  = nt + (size_t)b0 * ZZ + z;
    const float* pzp = nt + (size_t)b0 * ZZ + zp;

    // Two independent batch elements per iteration (ILP to cover the
    // dependency chain; kernel is latency/issue-bound at occ ~20%).
    for (int b = b0; b < bend; b += 2) {
        const float x0a = __ldg(pz);
        const float x1a = __ldg(pzp);
        const float x0b = __ldg(pz + ZZ);
        const float x1b = __ldg(pzp + ZZ);
        pz  += 2 * ZZ;
        pzp += 2 * ZZ;
        const float x0[2] = {x0a, x0b};
        const float x1[2] = {x1a, x1b};

        // layer 1: tanh(W1^T x + b1)  [HW tanh: 1 MUFU each]
        float h[2][4];
        #pragma unroll
        for (int i = 0; i < 4; ++i) {
            #pragma unroll
            for (int u = 0; u < 2; ++u)
                h[u][i] = tanh_hw(fmaf(w1x[i], x0[u], fmaf(w1y[i], x1[u], b1a[i])));
        }

        // LN1 (gamma/beta folded into layer 2)
        #pragma unroll
        for (int u = 0; u < 2; ++u) {
            float m = (h[u][0] + h[u][1] + h[u][2] + h[u][3]) * 0.25f;
            float v = 0.0f;
            #pragma unroll
            for (int i = 0; i < 4; ++i) { h[u][i] -= m; v = fmaf(h[u][i], h[u][i], v); }
            float r = fast_rsqrt(fmaf(v, 0.25f, 1e-5f));
            #pragma unroll
            for (int i = 0; i < 4; ++i) h[u][i] *= r;
        }

        // layer 2: tanh(W2f^T h + b2f)  [HW tanh]
        float h2[2][4];
        #pragma unroll
        for (int k = 0; k < 4; ++k) {
            #pragma unroll
            for (int u = 0; u < 2; ++u) {
                float pre = b2f[k];
                #pragma unroll
                for (int i = 0; i < 4; ++i) pre = fmaf(h[u][i], W2f[i * 4 + k], pre);
                h2[u][k] = tanh_hw(pre);
            }
        }

        // LN2 (gamma/beta folded into heads)
        #pragma unroll
        for (int u = 0; u < 2; ++u) {
            float m = (h2[u][0] + h2[u][1] + h2[u][2] + h2[u][3]) * 0.25f;
            float v = 0.0f;
            #pragma unroll
            for (int k = 0; k < 4; ++k) { h2[u][k] -= m; v = fmaf(h2[u][k], h2[u][k], v); }
            float r = fast_rsqrt(fmaf(v, 0.25f, 1e-5f));
            #pragma unroll
            for (int k = 0; k < 4; ++k) h2[u][k] *= r;
        }

        #pragma unroll
        for (int u = 0; u < 2; ++u) {
            // heads
            float pl[4], xl[4];
            #pragma unroll
            for (int o = 0; o < 4; ++o) { pl[o] = bpf[o]; xl[o] = bxf[o]; }
            #pragma unroll
            for (int k = 0; k < 4; ++k) {
                #pragma unroll
                for (int o = 0; o < 4; ++o) {
                    pl[o] = fmaf(h2[u][k], Wpf[k * 4 + o], pl[o]);
                    xl[o] = fmaf(h2[u][k], Wxf[k * 4 + o], xl[o]);
                }
            }

            // log-softmax + softmax (logits are O(0.5): no max-shift needed;
            // mathematically identical to the stable form)
            float e[4], s = 0.0f;
            #pragma unroll
            for (int o = 0; o < 4; ++o) { e[o] = __expf(pl[o]); s += e[o]; }
            float inv = fast_rcp(s);
            float ls  = __logf(s);

            float4 piv = make_float4(e[0] * inv, e[1] * inv, e[2] * inv, e[3] * inv);
            float4 lpv = make_float4(pl[0] - ls, pl[1] - ls, pl[2] - ls, pl[3] - ls);

            // sigmoid head: xl already = (Wxi.h2 + bxi)/2; sigmoid = 0.5*tanh+0.5
            float4 xiv = make_float4(fmaf(tanh_hw(xl[0]), 0.5f, 0.5f),
                                     fmaf(tanh_hw(xl[1]), 0.5f, 0.5f),
                                     fmaf(tanh_hw(xl[2]), 0.5f, 0.5f),
                                     fmaf(tanh_hw(xl[3]), 0.5f, 0.5f));

            store_cs(pPi + (size_t)u * STEP, piv);
            store_cs(pLp + (size_t)u * STEP, lpv);
            store_cs(pXi + (size_t)u * STEP, xiv);
        }
        pPi += 2 * STEP;
        pLp += 2 * STEP;
        pXi += 2 * STEP;
    }
}

extern "C" void kernel_launch(void* const* d_in, const int* in_sizes, int n_in,
                              void* d_out, int out_size)
{
    const float* nt  = (const float*)d_in[0];
    const float* W1  = (const float*)d_in[1];
    const float* b1  = (const float*)d_in[2];
    const float* g1  = (const float*)d_in[3];
    const float* be1 = (const float*)d_in[4];
    const float* W2  = (const float*)d_in[5];
    const float* b2  = (const float*)d_in[6];
    const float* g2  = (const float*)d_in[7];
    const float* be2 = (const float*)d_in[8];
    const float* Wpi = (const float*)d_in[9];
    const float* bpi = (const float*)d_in[10];
    const float* Wxi = (const float*)d_in[11];
    const float* bxi = (const float*)d_in[12];
    float* out = (float*)d_out;

    const int nB = in_sizes[0] / ZZ;   // 2048

    dim3 block(128);
    dim3 grid((ZZ * ZZ) / 128, (nB + BCH - 1) / BCH);
    mlp_pairs_kernel<<<grid, block>>>(nt, W1, b1, g1, be1, W2, b2, g2, be2,
                                      Wpi, bpi, Wxi, bxi, out, nB);
}

// round 16
// speedup vs baseline: 1.0866x; 1.0866x over previous
#include <cuda_runtime.h>

// network_5299989643808: per-(z,zp)-pair tiny MLP over batch B.
// R15 (= R13 resubmit after infra failure): R9 base (72.2us: all tanh via
// single-MUFU tanh.approx, folded LN, pointer-increment addressing, streaming
// stores) + BCH 128->64 so the grid (1024 blocks) keeps all SMs at full
// 4-CTA/16-warp residency instead of the 3.46-CTA average of the 512-block
// grid. Kernel is near the DRAM roof (402MB writes, ~70% HBM); this raises
// memory-system concurrency.

static constexpr int ZZ  = 64;   // zones
static constexpr int BCH = 64;   // batch elements per block (y-dim chunk)

__device__ __forceinline__ float fast_rsqrt(float x) {
    float r; asm("rsqrt.approx.f32 %0, %1;" : "=f"(r) : "f"(x)); return r;
}
__device__ __forceinline__ float fast_rcp(float x) {
    float r; asm("rcp.approx.f32 %0, %1;" : "=f"(r) : "f"(x)); return r;
}
// HW tanh: 1 MUFU op; ~1e-7 accurate for this network's small arguments
// (empirically validated in R8/R9).
__device__ __forceinline__ float tanh_hw(float x) {
    float r; asm("tanh.approx.f32 %0, %1;" : "=f"(r) : "f"(x)); return r;
}
// Streaming 128-bit store (output is write-once, never re-read).
__device__ __forceinline__ void store_cs(float4* p, float4 v) {
    asm volatile("st.global.cs.v4.f32 [%0], {%1, %2, %3, %4};"
                 :: "l"(p), "f"(v.x), "f"(v.y), "f"(v.z), "f"(v.w) : "memory");
}

__global__ __launch_bounds__(128, 4)
void mlp_pairs_kernel(
    const float* __restrict__ nt,
    const float* __restrict__ W1,  const float* __restrict__ b1,
    const float* __restrict__ g1,  const float* __restrict__ be1,
    const float* __restrict__ W2,  const float* __restrict__ b2,
    const float* __restrict__ g2,  const float* __restrict__ be2,
    const float* __restrict__ Wpi, const float* __restrict__ bpi,
    const float* __restrict__ Wxi, const float* __restrict__ bxi,
    float* __restrict__ out, int nB)
{
    const int p  = blockIdx.x * blockDim.x + threadIdx.x;  // pair index 0..4095
    const int z  = p >> 6;
    const int zp = p & 63;

    // ---- Load weights for this pair, folding LN gamma/beta forward ----
    const float4* W1v = reinterpret_cast<const float4*>(W1) + (size_t)p * 2;
    float4 w1a = W1v[0];
    float4 w1b = W1v[1];
    float4 b1v = reinterpret_cast<const float4*>(b1)[p];
    float4 g1v = reinterpret_cast<const float4*>(g1)[p];
    float4 e1v = reinterpret_cast<const float4*>(be1)[p];
    float4 g2v = reinterpret_cast<const float4*>(g2)[p];
    float4 e2v = reinterpret_cast<const float4*>(be2)[p];

    const float g1a[4] = {g1v.x, g1v.y, g1v.z, g1v.w};
    const float e1a[4] = {e1v.x, e1v.y, e1v.z, e1v.w};
    const float g2a[4] = {g2v.x, g2v.y, g2v.z, g2v.w};
    const float e2a[4] = {e2v.x, e2v.y, e2v.z, e2v.w};

    // W2 folded: W2f[i][k] = W2[i][k]*g1[i];  b2f[k] = b2[k] + sum_i be1[i]*W2[i][k]
    float W2f[16], b2f[4];
    {
        float4 b2v = reinterpret_cast<const float4*>(b2)[p];
        b2f[0] = b2v.x; b2f[1] = b2v.y; b2f[2] = b2v.z; b2f[3] = b2v.w;
        const float4* W2v = reinterpret_cast<const float4*>(W2) + (size_t)p * 4;
        #pragma unroll
        for (int i = 0; i < 4; ++i) {
            float4 row = W2v[i];
            float rr[4] = {row.x, row.y, row.z, row.w};
            #pragma unroll
            for (int k = 0; k < 4; ++k) {
                W2f[i * 4 + k] = rr[k] * g1a[i];
                b2f[k] = fmaf(e1a[i], rr[k], b2f[k]);
            }
        }
    }
    // Heads folded with g2/be2. Sigmoid head additionally pre-scaled by 0.5:
    // sigmoid(x) = 0.5*tanh(x/2) + 0.5, so fold the /2 into Wxf/bxf.
    float Wpf[16], bpf[4], Wxf[16], bxf[4];
    {
        float4 bpv = reinterpret_cast<const float4*>(bpi)[p];
        float4 bxv = reinterpret_cast<const float4*>(bxi)[p];
        bpf[0] = bpv.x; bpf[1] = bpv.y; bpf[2] = bpv.z; bpf[3] = bpv.w;
        bxf[0] = 0.5f * bxv.x; bxf[1] = 0.5f * bxv.y;
        bxf[2] = 0.5f * bxv.z; bxf[3] = 0.5f * bxv.w;
        const float4* Wpv = reinterpret_cast<const float4*>(Wpi) + (size_t)p * 4;
        const float4* Wxv = reinterpret_cast<const float4*>(Wxi) + (size_t)p * 4;
        #pragma unroll
        for (int k = 0; k < 4; ++k) {
            float4 rp = Wpv[k];
            float rpa[4] = {rp.x, rp.y, rp.z, rp.w};
            float4 rx = Wxv[k];
            float rxa[4] = {rx.x, rx.y, rx.z, rx.w};
            const float g2h = 0.5f * g2a[k];
            const float e2h = 0.5f * e2a[k];
            #pragma unroll
            for (int o = 0; o < 4; ++o) {
                Wpf[k * 4 + o] = rpa[o] * g2a[k];
                bpf[o] = fmaf(e2a[k], rpa[o], bpf[o]);
                Wxf[k * 4 + o] = rxa[o] * g2h;
                bxf[o] = fmaf(e2h, rxa[o], bxf[o]);
            }
        }
    }

    const float w1x[4] = {w1a.x, w1a.y, w1a.z, w1a.w};
    const float w1y[4] = {w1b.x, w1b.y, w1b.z, w1b.w};
    const float b1a[4] = {b1v.x, b1v.y, b1v.z, b1v.w};

    const size_t N4   = (size_t)nB * ZZ * ZZ;      // float4 count per tensor
    const int    STEP = ZZ * ZZ;                   // float4 stride per batch element

    const int b0   = blockIdx.y * BCH;
    const int bend = (b0 + BCH < nB) ? (b0 + BCH) : nB;

    // Incremented pointers: no per-iteration index arithmetic.
    float4* pPi = reinterpret_cast<float4*>(out) + (size_t)b0 * STEP + ((size_t)z * ZZ + zp);
    float4* pLp = pPi + N4;
    float4* pXi = pPi + 2 * N4;
    const float* pz  = nt + (size_t)b0 * ZZ + z;
    const float* pzp = nt + (size_t)b0 * ZZ + zp;

    // Two independent batch elements per iteration (ILP to cover the
    // dependency chain).
    for (int b = b0; b < bend; b += 2) {
        const float x0a = __ldg(pz);
        const float x1a = __ldg(pzp);
        const float x0b = __ldg(pz + ZZ);
        const float x1b = __ldg(pzp + ZZ);
        pz  += 2 * ZZ;
        pzp += 2 * ZZ;
        const float x0[2] = {x0a, x0b};
        const float x1[2] = {x1a, x1b};

        // layer 1: tanh(W1^T x + b1)  [HW tanh: 1 MUFU each]
        float h[2][4];
        #pragma unroll
        for (int i = 0; i < 4; ++i) {
            #pragma unroll
            for (int u = 0; u < 2; ++u)
                h[u][i] = tanh_hw(fmaf(w1x[i], x0[u], fmaf(w1y[i], x1[u], b1a[i])));
        }

        // LN1 (gamma/beta folded into layer 2)
        #pragma unroll
        for (int u = 0; u < 2; ++u) {
            float m = (h[u][0] + h[u][1] + h[u][2] + h[u][3]) * 0.25f;
            float v = 0.0f;
            #pragma unroll
            for (int i = 0; i < 4; ++i) { h[u][i] -= m; v = fmaf(h[u][i], h[u][i], v); }
            float r = fast_rsqrt(fmaf(v, 0.25f, 1e-5f));
            #pragma unroll
            for (int i = 0; i < 4; ++i) h[u][i] *= r;
        }

        // layer 2: tanh(W2f^T h + b2f)  [HW tanh]
        float h2[2][4];
        #pragma unroll
        for (int k = 0; k < 4; ++k) {
            #pragma unroll
            for (int u = 0; u < 2; ++u) {
                float pre = b2f[k];
                #pragma unroll
                for (int i = 0; i < 4; ++i) pre = fmaf(h[u][i], W2f[i * 4 + k], pre);
                h2[u][k] = tanh_hw(pre);
            }
        }

        // LN2 (gamma/beta folded into heads)
        #pragma unroll
        for (int u = 0; u < 2; ++u) {
            float m = (h2[u][0] + h2[u][1] + h2[u][2] + h2[u][3]) * 0.25f;
            float v = 0.0f;
            #pragma unroll
            for (int k = 0; k < 4; ++k) { h2[u][k] -= m; v = fmaf(h2[u][k], h2[u][k], v); }
            float r = fast_rsqrt(fmaf(v, 0.25f, 1e-5f));
            #pragma unroll
            for (int k = 0; k < 4; ++k) h2[u][k] *= r;
        }

        #pragma unroll
        for (int u = 0; u < 2; ++u) {
            // heads
            float pl[4], xl[4];
            #pragma unroll
            for (int o = 0; o < 4; ++o) { pl[o] = bpf[o]; xl[o] = bxf[o]; }
            #pragma unroll
            for (int k = 0; k < 4; ++k) {
                #pragma unroll
                for (int o = 0; o < 4; ++o) {
                    pl[o] = fmaf(h2[u][k], Wpf[k * 4 + o], pl[o]);
                    xl[o] = fmaf(h2[u][k], Wxf[k * 4 + o], xl[o]);
                }
            }

            // log-softmax + softmax (logits are O(0.5): no max-shift needed;
            // mathematically identical to the stable form)
            float e[4], s = 0.0f;
            #pragma unroll
            for (int o = 0; o < 4; ++o) { e[o] = __expf(pl[o]); s += e[o]; }
            float inv = fast_rcp(s);
            float ls  = __logf(s);

            float4 piv = make_float4(e[0] * inv, e[1] * inv, e[2] * inv, e[3] * inv);
            float4 lpv = make_float4(pl[0] - ls, pl[1] - ls, pl[2] - ls, pl[3] - ls);

            // sigmoid head: xl already = (Wxi.h2 + bxi)/2; sigmoid = 0.5*tanh+0.5
            float4 xiv = make_float4(fmaf(tanh_hw(xl[0]), 0.5f, 0.5f),
                                     fmaf(tanh_hw(xl[1]), 0.5f, 0.5f),
                                     fmaf(tanh_hw(xl[2]), 0.5f, 0.5f),
                                     fmaf(tanh_hw(xl[3]), 0.5f, 0.5f));

            store_cs(pPi + (size_t)u * STEP, piv);
            store_cs(pLp + (size_t)u * STEP, lpv);
            store_cs(pXi + (size_t)u * STEP, xiv);
        }
        pPi += 2 * STEP;
        pLp += 2 * STEP;
        pXi += 2 * STEP;
    }
}

extern "C" void kernel_launch(void* const* d_in, const int* in_sizes, int n_in,
                              void* d_out, int out_size)
{
    const float* nt  = (const float*)d_in[0];
    const float* W1  = (const float*)d_in[1];
    const float* b1  = (const float*)d_in[2];
    const float* g1  = (const float*)d_in[3];
    const float* be1 = (const float*)d_in[4];
    const float* W2  = (const float*)d_in[5];
    const float* b2  = (const float*)d_in[6];
    const float* g2  = (const float*)d_in[7];
    const float* be2 = (const float*)d_in[8];
    const float* Wpi = (const float*)d_in[9];
    const float* bpi = (const float*)d_in[10];
    const float* Wxi = (const float*)d_in[11];
    const float* bxi = (const float*)d_in[12];
    float* out = (float*)d_out;

    const int nB = in_sizes[0] / ZZ;   // 2048

    dim3 block(128);
    dim3 grid((ZZ * ZZ) / 128, (nB + BCH - 1) / BCH);
    mlp_pairs_kernel<<<grid, block>>>(nt, W1, b1, g1, be1, W2, b2, g2, be2,
                                      Wpi, bpi, Wxi, bxi, out, nB);
}